// round 5
// baseline (speedup 1.0000x reference)
#include <cuda_runtime.h>

#define DTV      0.02f
#define SQRT_DT  0.141421356237309515f
#define SIGMA    0.5f
#define NSTEP    50
#define BATCH    4096
#define PPC      32            // paths per CTA
#define NCTA     (BATCH / PPC) // 128
#define NTHR     512

typedef unsigned long long u64;

// ---- shared-memory layout (float offsets) ----
#define W_IN   0       // [2][64] = 128
#define B_IN   128     // 64
#define W_H    192     // [3][64][64] = 12288
#define B_H    12480   // [3][64] = 192
#define W_OUT  12672   // 64
#define B_OUT  12736   // 1 (+3 pad)
#define NET_SZ 12740
// activations: dup'd pairs {x,x}, [64 rows][32 u64], XOR-swizzled 16B chunks
#define XBUF     4096
#define OFF_X    (2 * NET_SZ)
#define OFF_DX   (OFF_X   + XBUF)
#define OFF_XN   (OFF_DX  + XBUF)
#define OFF_DXN  (OFF_XN  + XBUF)
#define OFF_QX   (OFF_DXN + XBUF)
#define OFF_QXN  (OFF_QX  + XBUF)
#define OFF_YS   (OFF_QXN + XBUF)
#define OFF_HD2  (OFF_YS  + 32)       // [2 halves][3 heads][32] partials
#define SMEM_FLOATS (OFF_HD2 + 192)
#define SMEM_BYTES  (SMEM_FLOATS * 4)

__device__ float g_part[NCTA];
__device__ int   g_count = 0;

__device__ __forceinline__ void cpf(float* d, const float* s, int n, int tid) {
    for (int i = tid; i < n; i += NTHR) d[i] = s[i];
}

__device__ __forceinline__ u64 fma2(u64 a, u64 b, u64 c) {
    u64 d;
    asm("fma.rn.f32x2 %0, %1, %2, %3;" : "=l"(d) : "l"(a), "l"(b), "l"(c));
    return d;
}
__device__ __forceinline__ u64 add2(u64 a, u64 b) {
    u64 d;
    asm("add.rn.f32x2 %0, %1, %2;" : "=l"(d) : "l"(a), "l"(b));
    return d;
}
__device__ __forceinline__ u64 pk(float lo, float hi) {
    u64 r;
    asm("mov.b64 %0, {%1, %2};" : "=l"(r) : "f"(lo), "f"(hi));
    return r;
}
__device__ __forceinline__ void upk(u64 v, float& lo, float& hi) {
    asm("mov.b64 {%0, %1}, %2;" : "=f"(lo), "=f"(hi) : "l"(v));
}
__device__ __forceinline__ u64 shx(u64 v, int m) {
    return (u64)__shfl_xor_sync(0xffffffffu, (unsigned long long)v, m);
}

// swizzled 16B-chunk index within a 64-row x 256B activation buffer
__device__ __forceinline__ int swz(int c, int r) { return c ^ ((r >> 2) & 15); }

// Fused hidden layer: 4-way K-split within each warp, shuffle-reduced.
// Lane = pg*4+chunk: K-range [chunk*16, chunk*16+16), paths 4pg..4pg+3.
// Row-pair-packed accumulators; stage1 (xor1) splits row-pairs, stage2 (xor2)
// splits path-pairs. Each lane finishes 2 rows x 2 paths.
__device__ __forceinline__ void fused_layer(
    const float* __restrict__ Wy, const float* __restrict__ by,
    const float* __restrict__ Wq, const float* __restrict__ bq,
    const float* __restrict__ X,  const float* __restrict__ dXb,
    const float* __restrict__ QX,
    float* __restrict__ Xn, float* __restrict__ dXn, float* __restrict__ QXn,
    int jg, int pg, int chunk)
{
    const ulonglong2* WY2 = (const ulonglong2*)Wy;
    const ulonglong2* WQ2 = (const ulonglong2*)Wq;
    const ulonglong2* X2  = (const ulonglong2*)X;
    const ulonglong2* dX2 = (const ulonglong2*)dXb;
    const ulonglong2* QX2 = (const ulonglong2*)QX;

    const int j0 = jg * 4;
    const int ib = chunk * 16;

    u64 ah[2][4], ad[2][4], aq[2][4];
#pragma unroll
    for (int p = 0; p < 4; p++) {
        ah[0][p] = 0ull; ah[1][p] = 0ull;
        ad[0][p] = 0ull; ad[1][p] = 0ull;
        aq[0][p] = 0ull; aq[1][p] = 0ull;
    }
    if (chunk == 0) {
        u64 by01 = pk(by[j0], by[j0 + 1]);
        u64 bq01 = pk(bq[j0], bq[j0 + 1]);
#pragma unroll
        for (int p = 0; p < 4; p++) { ah[0][p] = by01; aq[0][p] = bq01; }
    } else if (chunk == 1) {
        u64 by23 = pk(by[j0 + 2], by[j0 + 3]);
        u64 bq23 = pk(bq[j0 + 2], bq[j0 + 3]);
#pragma unroll
        for (int p = 0; p < 4; p++) { ah[1][p] = by23; aq[1][p] = bq23; }
    }

#pragma unroll 4
    for (int k = 0; k < 16; k++) {
        int i = ib + k;
        ulonglong2 wY = WY2[i * 16 + jg];        // warp-uniform (jg per warp)
        ulonglong2 wQ = WQ2[i * 16 + jg];
        int c0 = swz(pg * 2, i);
        int c1 = swz(pg * 2 + 1, i);
        ulonglong2 xa = X2[i * 16 + c0];
        ulonglong2 xb = X2[i * 16 + c1];
        ulonglong2 da = dX2[i * 16 + c0];
        ulonglong2 db = dX2[i * 16 + c1];
        ulonglong2 qa = QX2[i * 16 + c0];
        ulonglong2 qb = QX2[i * 16 + c1];
        u64 xd[4] = {xa.x, xa.y, xb.x, xb.y};
        u64 dd[4] = {da.x, da.y, db.x, db.y};
        u64 qd[4] = {qa.x, qa.y, qb.x, qb.y};
#pragma unroll
        for (int p = 0; p < 4; p++) {
            ah[0][p] = fma2(wY.x, xd[p], ah[0][p]);
            ah[1][p] = fma2(wY.y, xd[p], ah[1][p]);
            ad[0][p] = fma2(wY.x, dd[p], ad[0][p]);
            ad[1][p] = fma2(wY.y, dd[p], ad[1][p]);
            aq[0][p] = fma2(wQ.x, qd[p], aq[0][p]);
            aq[1][p] = fma2(wQ.y, qd[p], aq[1][p]);
        }
    }

    // ---- stage 1: xor 1, keep row-pair kp = chunk&1 ----
    const int kp = chunk & 1;
    u64 kh[4], kd[4], kq[4];
#pragma unroll
    for (int p = 0; p < 4; p++) {
        u64 o0 = shx(ah[0][p], 1), o1 = shx(ah[1][p], 1);
        kh[p] = add2(kp ? ah[1][p] : ah[0][p], kp ? o1 : o0);
        u64 e0 = shx(ad[0][p], 1), e1 = shx(ad[1][p], 1);
        kd[p] = add2(kp ? ad[1][p] : ad[0][p], kp ? e1 : e0);
        u64 f0 = shx(aq[0][p], 1), f1 = shx(aq[1][p], 1);
        kq[p] = add2(kp ? aq[1][p] : aq[0][p], kp ? f1 : f0);
    }

    // ---- stage 2: xor 2, keep path-half ph = chunk>>1 ----
    const int ph = chunk >> 1;
    u64 fh[2], fd[2], fq[2];
    {
        u64 sh_[4], sd_[4], sq_[4];
#pragma unroll
        for (int p = 0; p < 4; p++) {
            sh_[p] = shx(kh[p], 2);
            sd_[p] = shx(kd[p], 2);
            sq_[p] = shx(kq[p], 2);
        }
#pragma unroll
        for (int t = 0; t < 2; t++) {
            int pi = ph * 2 + t;
            fh[t] = add2(kh[pi], sh_[pi]);
            fd[t] = add2(kd[pi], sd_[pi]);
            fq[t] = add2(kq[pi], sq_[pi]);
        }
    }

    // ---- epilogue: 2 rows x 2 paths per lane ----
    const int rbase = j0 + 2 * kp;
    const int pp = pg * 2 + ph;      // 16B chunk index (covers paths 2pp,2pp+1)
    float h0[2], h1[2], d0[2], d1[2], q0[2], q1[2];
#pragma unroll
    for (int t = 0; t < 2; t++) {
        upk(fh[t], h0[t], h1[t]);    // lo = row rbase, hi = rbase+1
        upk(fd[t], d0[t], d1[t]);
        upk(fq[t], q0[t], q1[t]);
    }
    ulonglong2* Xn2  = (ulonglong2*)Xn;
    ulonglong2* dXn2 = (ulonglong2*)dXn;
    ulonglong2* QXn2 = (ulonglong2*)QXn;
#pragma unroll
    for (int rr = 0; rr < 2; rr++) {
        int r = rbase + rr;
        int cc = swz(pp, r);
        float sa, ca, sb, cb;
        __sincosf(rr ? h1[0] : h0[0], &sa, &ca);
        __sincosf(rr ? h1[1] : h0[1], &sb, &cb);
        float qsa = __sinf(rr ? q1[0] : q0[0]);
        float qsb = __sinf(rr ? q1[1] : q0[1]);
        float dva = ca * (rr ? d1[0] : d0[0]);
        float dvb = cb * (rr ? d1[1] : d0[1]);
        Xn2[r * 16 + cc]  = make_ulonglong2(pk(sa, sa), pk(sb, sb));
        dXn2[r * 16 + cc] = make_ulonglong2(pk(dva, dva), pk(dvb, dvb));
        QXn2[r * 16 + cc] = make_ulonglong2(pk(qsa, qsa), pk(qsb, qsb));
    }
}

// Fused full-net eval; ends with HD2 partials written and CTA synced.
__device__ __forceinline__ void eval_fused(float* sm, float tval,
                                           int jg, int pg, int chunk,
                                           int wid, int lane)
{
    const float* netY = sm;
    const float* netQ = sm + NET_SZ;
    float* X   = sm + OFF_X;
    float* dXb = sm + OFF_DX;
    float* Xn  = sm + OFF_XN;
    float* dXn = sm + OFF_DXN;
    float* QX  = sm + OFF_QX;
    float* QXn = sm + OFF_QXN;
    const float* ys = sm + OFF_YS;

    // ---- input layer: each thread does 1 row x 4 paths ----
    {
        int r = jg * 4 + chunk;
        int p0 = pg * 4;
        float yv[4] = {ys[p0], ys[p0 + 1], ys[p0 + 2], ys[p0 + 3]};
        float wtY = netY[W_IN + r], wyY = netY[W_IN + 64 + r];
        float tbY = fmaf(tval, wtY, netY[B_IN + r]);
        float wtQ = netQ[W_IN + r], wyQ = netQ[W_IN + 64 + r];
        float tbQ = fmaf(tval, wtQ, netQ[B_IN + r]);
        float s[4], c[4], sq[4];
#pragma unroll
        for (int p = 0; p < 4; p++) {
            __sincosf(fmaf(yv[p], wyY, tbY), &s[p], &c[p]);
            sq[p] = __sinf(fmaf(yv[p], wyQ, tbQ));
        }
        ulonglong2* X2  = (ulonglong2*)X;
        ulonglong2* dX2 = (ulonglong2*)dXb;
        ulonglong2* QX2 = (ulonglong2*)QX;
        int cc0 = swz(pg * 2, r), cc1 = swz(pg * 2 + 1, r);
        X2[r * 16 + cc0] = make_ulonglong2(pk(s[0], s[0]), pk(s[1], s[1]));
        X2[r * 16 + cc1] = make_ulonglong2(pk(s[2], s[2]), pk(s[3], s[3]));
        float d0 = c[0] * wyY, d1 = c[1] * wyY, d2 = c[2] * wyY, d3 = c[3] * wyY;
        dX2[r * 16 + cc0] = make_ulonglong2(pk(d0, d0), pk(d1, d1));
        dX2[r * 16 + cc1] = make_ulonglong2(pk(d2, d2), pk(d3, d3));
        QX2[r * 16 + cc0] = make_ulonglong2(pk(sq[0], sq[0]), pk(sq[1], sq[1]));
        QX2[r * 16 + cc1] = make_ulonglong2(pk(sq[2], sq[2]), pk(sq[3], sq[3]));
    }
    __syncthreads();
    fused_layer(netY + W_H,        netY + B_H,       netQ + W_H,        netQ + B_H,
                X, dXb, QX, Xn, dXn, QXn, jg, pg, chunk);
    __syncthreads();
    fused_layer(netY + W_H + 4096, netY + B_H + 64,  netQ + W_H + 4096, netQ + B_H + 64,
                Xn, dXn, QXn, X, dXb, QX, jg, pg, chunk);
    __syncthreads();
    fused_layer(netY + W_H + 8192, netY + B_H + 128, netQ + W_H + 8192, netQ + B_H + 128,
                X, dXb, QX, Xn, dXn, QXn, jg, pg, chunk);
    __syncthreads();

    // ---- head partials: warps 0-5 = (half h2, head) x 32 paths ----
    if (wid < 6) {
        int head = wid % 3, h2 = wid / 3;
        const float* src = (head == 0) ? Xn : (head == 1) ? dXn : QXn;
        const float* wv  = (head == 2) ? (netQ + W_OUT) : (netY + W_OUT);
        int p = lane;
        int i0 = h2 * 32;
        float a0 = 0.0f, a1 = 0.0f, a2 = 0.0f, a3 = 0.0f;
#pragma unroll 4
        for (int i = 0; i < 32; i += 4) {
#pragma unroll
            for (int k = 0; k < 4; k++) {
                int ii = i0 + i + k;
                int off = ii * 64 + swz(p >> 1, ii) * 4 + (p & 1) * 2;
                float v = src[off] * wv[ii];
                if (k == 0) a0 += v; else if (k == 1) a1 += v;
                else if (k == 2) a2 += v; else a3 += v;
            }
        }
        sm[OFF_HD2 + h2 * 96 + head * 32 + p] = (a0 + a1) + (a2 + a3);
    }
    __syncthreads();
}

__global__ __launch_bounds__(NTHR, 1) void fbsnn_main(
    const float* __restrict__ yWin,  const float* __restrict__ yBin,
    const float* __restrict__ yWh,   const float* __restrict__ yBh,
    const float* __restrict__ yWout, const float* __restrict__ yBout,
    const float* __restrict__ qWin,  const float* __restrict__ qBin,
    const float* __restrict__ qWh,   const float* __restrict__ qBh,
    const float* __restrict__ qWout, const float* __restrict__ qBout,
    const float* __restrict__ y0,    const float* __restrict__ dW,
    float* __restrict__ out)
{
    extern __shared__ float sm[];
    const int tid = threadIdx.x;
    const int wid = tid >> 5;
    const int lane = tid & 31;
    const int jg = wid;           // 16 warps = 16 row-groups of 4
    const int pg = lane >> 2;     // 8 path-groups of 4
    const int chunk = lane & 3;   // 4-way K-split

    // ---- stage all weights into smem once ----
    cpf(sm + W_IN,  yWin, 128,   tid);
    cpf(sm + B_IN,  yBin, 64,    tid);
    cpf(sm + W_H,   yWh,  12288, tid);
    cpf(sm + B_H,   yBh,  192,   tid);
    cpf(sm + W_OUT, yWout, 64,   tid);
    if (tid == 0) sm[B_OUT] = yBout[0];
    float* smq = sm + NET_SZ;
    cpf(smq + W_IN,  qWin, 128,   tid);
    cpf(smq + B_IN,  qBin, 64,    tid);
    cpf(smq + W_H,   qWh,  12288, tid);
    cpf(smq + B_H,   qBh,  192,   tid);
    cpf(smq + W_OUT, qWout, 64,   tid);
    if (tid == 0) smq[B_OUT] = qBout[0];
    if (tid < 32) sm[OFF_YS + tid] = y0[0];
    __syncthreads();

    const int pbase = blockIdx.x * PPC;
    const float* HD2 = sm + OFF_HD2;

    float lossAcc = 0.0f, Ytilde = 0.0f;
    float dwcur = 0.0f;
    if (wid == 0) dwcur = dW[pbase + lane];   // prefetch step 0

    // initial fused eval at t = 0: HD2 holds Y0|dY0|q0 partials
    eval_fused(sm, 0.0f, jg, pg, chunk, wid, lane);

    for (int n = 0; n < NSTEP; n++) {
        if (wid == 0) {
            int p = lane;
            float Yv  = HD2[p]      + HD2[96 + p]  + sm[B_OUT];
            float dYv = HD2[32 + p] + HD2[128 + p];
            float qv  = HD2[64 + p] + HD2[160 + p] + smq[B_OUT];
            if (n > 0) {
                float e = Yv - Ytilde;
                lossAcc = fmaf(e, e, lossAcc);
            }
            float dwn = SQRT_DT * dwcur;
            Ytilde = Yv - qv * qv * DTV + SIGMA * dYv * dwn;
            sm[OFF_YS + p] += qv * DTV + SIGMA * dwn;
            if (n + 1 < NSTEP) dwcur = dW[(n + 1) * BATCH + pbase + p];
        }
        __syncthreads();

        eval_fused(sm, (float)(n + 1) * DTV, jg, pg, chunk, wid, lane);
    }

    if (wid == 0) {
        int p = lane;
        float Yv  = HD2[p]      + HD2[96 + p]  + sm[B_OUT];
        float dYv = HD2[32 + p] + HD2[128 + p];
        float e = Yv - Ytilde;
        lossAcc = fmaf(e, e, lossAcc);
        float yN = sm[OFF_YS + p];
        float e1 = Yv - yN * yN;
        float e2 = dYv - 2.0f * yN;
        lossAcc = fmaf(e1, e1, fmaf(e2, e2, lossAcc));
#pragma unroll
        for (int o = 16; o > 0; o >>= 1)
            lossAcc += __shfl_down_sync(0xffffffffu, lossAcc, o);
        if (lane == 0) g_part[blockIdx.x] = lossAcc;
    }

    // ---- last-CTA deterministic reduction (single launch) ----
    if (tid == 0) {
        __threadfence();
        int old = atomicAdd(&g_count, 1);
        if (old == NCTA - 1) {
            __threadfence();
            float acc = 0.0f;
#pragma unroll 8
            for (int i = 0; i < NCTA; i++) acc += g_part[i];
            out[0] = acc * (1.0f / (float)BATCH);
            g_count = 0;
        }
    }
}

extern "C" void kernel_launch(void* const* d_in, const int* in_sizes, int n_in,
                              void* d_out, int out_size)
{
    const float *yWin, *yBin, *yWh, *yBh, *yWout, *yBout;
    const float *qWin, *qBin, *qWh, *qBh, *qWout, *qBout;
    const float *y0, *dW;

    if (in_sizes[0] == 1) {
        y0    = (const float*)d_in[0];
        yWin  = (const float*)d_in[1];
        yBin  = (const float*)d_in[2];
        yWh   = (const float*)d_in[3];
        yBh   = (const float*)d_in[4];
        yWout = (const float*)d_in[5];
        yBout = (const float*)d_in[6];
        qWin  = (const float*)d_in[7];
        qBin  = (const float*)d_in[8];
        qWh   = (const float*)d_in[9];
        qBh   = (const float*)d_in[10];
        qWout = (const float*)d_in[11];
        qBout = (const float*)d_in[12];
        dW    = (const float*)d_in[13];
    } else {
        yWin  = (const float*)d_in[0];
        yBin  = (const float*)d_in[1];
        yWh   = (const float*)d_in[2];
        yBh   = (const float*)d_in[3];
        yWout = (const float*)d_in[4];
        yBout = (const float*)d_in[5];
        qWin  = (const float*)d_in[6];
        qBin  = (const float*)d_in[7];
        qWh   = (const float*)d_in[8];
        qBh   = (const float*)d_in[9];
        qWout = (const float*)d_in[10];
        qBout = (const float*)d_in[11];
        y0    = (const float*)d_in[12];
        dW    = (const float*)d_in[13];
    }

    cudaFuncSetAttribute(fbsnn_main, cudaFuncAttributeMaxDynamicSharedMemorySize,
                         SMEM_BYTES);

    fbsnn_main<<<NCTA, NTHR, SMEM_BYTES>>>(yWin, yBin, yWh, yBh, yWout, yBout,
                                           qWin, qBin, qWh, qBh, qWout, qBout,
                                           y0, dW, (float*)d_out);
}

// round 6
// speedup vs baseline: 2.2296x; 2.2296x over previous
#include <cuda_runtime.h>

#define DTV      0.02f
#define SQRT_DT  0.141421356237309515f
#define SIGMA    0.5f
#define NSTEP    50
#define BATCH    4096
#define PPC      32            // paths per CTA
#define NCTA     (BATCH / PPC) // 128
#define NTHR     512

typedef unsigned long long u64;

// ---- shared-memory layout (float offsets) ----
#define W_IN   0       // [2][64] = 128
#define B_IN   128     // 64
#define W_H    192     // [3][64][64] = 12288
#define B_H    12480   // [3][64] = 192
#define W_OUT  12672   // 64
#define B_OUT  12736   // 1 (+3 pad)
#define NET_SZ 12740
// activations: dup'd pairs {x,x}, [64 rows][32 u64], XOR-swizzled 16B chunks
#define XBUF     4096
#define OFF_X    (2 * NET_SZ)           // 25480
#define OFF_DX   (OFF_X   + XBUF)
#define OFF_XN   (OFF_DX  + XBUF)
#define OFF_DXN  (OFF_XN  + XBUF)
#define OFF_QX   (OFF_DXN + XBUF)
#define OFF_QXN  (OFF_QX  + XBUF)
// K-half exchange: two [6][256] u64 buffers
#define OFF_EXA  (OFF_QXN + XBUF)       // 3072 floats
#define OFF_EXB  (OFF_EXA + 3072)       // 3072 floats
#define OFF_YS   (OFF_EXB + 3072)
#define OFF_HD2  (OFF_YS  + 32)         // [2 halves][3 heads][32]
#define SMEM_FLOATS (OFF_HD2 + 192)
#define SMEM_BYTES  (SMEM_FLOATS * 4)   // ~220 KB

__device__ float g_part[NCTA];
__device__ int   g_count = 0;

__device__ __forceinline__ void cpf(float* d, const float* s, int n, int tid) {
    for (int i = tid; i < n; i += NTHR) d[i] = s[i];
}

__device__ __forceinline__ u64 fma2(u64 a, u64 b, u64 c) {
    u64 d;
    asm("fma.rn.f32x2 %0, %1, %2, %3;" : "=l"(d) : "l"(a), "l"(b), "l"(c));
    return d;
}
__device__ __forceinline__ u64 add2(u64 a, u64 b) {
    u64 d;
    asm("add.rn.f32x2 %0, %1, %2;" : "=l"(d) : "l"(a), "l"(b));
    return d;
}
__device__ __forceinline__ u64 pk(float lo, float hi) {
    u64 r;
    asm("mov.b64 %0, {%1, %2};" : "=l"(r) : "f"(lo), "f"(hi));
    return r;
}
__device__ __forceinline__ void upk(u64 v, float& lo, float& hi) {
    asm("mov.b64 {%0, %1}, %2;" : "=f"(lo), "=f"(hi) : "l"(v));
}

// swizzled 16B-chunk index within a 64-row x 256B activation buffer
__device__ __forceinline__ int swz(int c, int r) { return c ^ ((r >> 2) & 15); }

// Fused hidden layer, warp-tiled:
// warp = (half, jwg, pwg): 16 j x 16 paths x K-half.  lane = (jsub:4, psub:8).
// Thread: 4 j (2 packed u64) x 2 paths x {h, dh, q} = 12 u64 accumulators.
// K-halves combined via smem exchange; each half finishes 2 of its 4 rows.
__device__ __forceinline__ void fused_layer(
    float* __restrict__ sm,
    const float* __restrict__ Wy, const float* __restrict__ by,
    const float* __restrict__ Wq, const float* __restrict__ bq,
    const float* __restrict__ X,  const float* __restrict__ dXb,
    const float* __restrict__ QX,
    float* __restrict__ Xn, float* __restrict__ dXn, float* __restrict__ QXn,
    int half, int j0, int pp, int jq, int xid)
{
    const ulonglong2* WY2 = (const ulonglong2*)Wy;
    const ulonglong2* WQ2 = (const ulonglong2*)Wq;
    const ulonglong2* X2  = (const ulonglong2*)X;
    const ulonglong2* dX2 = (const ulonglong2*)dXb;
    const ulonglong2* QX2 = (const ulonglong2*)QX;

    // acc[ju][pa]: ju=0 -> rows {j0,j0+1}, ju=1 -> {j0+2,j0+3}; pa = path idx
    u64 ah[2][2], ad[2][2], aq[2][2];
#pragma unroll
    for (int ju = 0; ju < 2; ju++)
#pragma unroll
        for (int pa = 0; pa < 2; pa++) {
            ah[ju][pa] = 0ull; ad[ju][pa] = 0ull; aq[ju][pa] = 0ull;
        }
    {   // bias folded into the KEPT pair of this half
        int jb = j0 + 2 * half;
        u64 byv = pk(by[jb], by[jb + 1]);
        u64 bqv = pk(bq[jb], bq[jb + 1]);
        ah[half][0] = byv; ah[half][1] = byv;
        aq[half][0] = bqv; aq[half][1] = bqv;
    }

    const int ib = half * 32;
#pragma unroll 4
    for (int k = 0; k < 32; k++) {
        int i = ib + k;
        ulonglong2 wY = WY2[i * 16 + jq];   // {wj0,wj1},{wj2,wj3}
        ulonglong2 wQ = WQ2[i * 16 + jq];
        int cc = swz(pp, i);
        ulonglong2 xv = X2[i * 16 + cc];    // {x_p0 dup},{x_p1 dup}
        ulonglong2 dv = dX2[i * 16 + cc];
        ulonglong2 qv = QX2[i * 16 + cc];
        ah[0][0] = fma2(wY.x, xv.x, ah[0][0]);
        ah[0][1] = fma2(wY.x, xv.y, ah[0][1]);
        ah[1][0] = fma2(wY.y, xv.x, ah[1][0]);
        ah[1][1] = fma2(wY.y, xv.y, ah[1][1]);
        ad[0][0] = fma2(wY.x, dv.x, ad[0][0]);
        ad[0][1] = fma2(wY.x, dv.y, ad[0][1]);
        ad[1][0] = fma2(wY.y, dv.x, ad[1][0]);
        ad[1][1] = fma2(wY.y, dv.y, ad[1][1]);
        aq[0][0] = fma2(wQ.x, qv.x, aq[0][0]);
        aq[0][1] = fma2(wQ.x, qv.y, aq[0][1]);
        aq[1][0] = fma2(wQ.y, qv.x, aq[1][0]);
        aq[1][1] = fma2(wQ.y, qv.y, aq[1][1]);
    }

    // ---- exchange: give away the non-kept ju, receive partner's ----
    u64* EXA = (u64*)(sm + OFF_EXA);   // written by half 0 (its ju=1)
    u64* EXB = (u64*)(sm + OFF_EXB);   // written by half 1 (its ju=0)
    if (half == 0) {
#pragma unroll
        for (int pa = 0; pa < 2; pa++) {
            EXA[(0 + pa) * 256 + xid] = ah[1][pa];
            EXA[(2 + pa) * 256 + xid] = ad[1][pa];
            EXA[(4 + pa) * 256 + xid] = aq[1][pa];
        }
    } else {
#pragma unroll
        for (int pa = 0; pa < 2; pa++) {
            EXB[(0 + pa) * 256 + xid] = ah[0][pa];
            EXB[(2 + pa) * 256 + xid] = ad[0][pa];
            EXB[(4 + pa) * 256 + xid] = aq[0][pa];
        }
    }
    __syncthreads();

    u64 fh[2], fd[2], fq[2];
    if (half == 0) {
#pragma unroll
        for (int pa = 0; pa < 2; pa++) {
            fh[pa] = add2(ah[0][pa], EXB[(0 + pa) * 256 + xid]);
            fd[pa] = add2(ad[0][pa], EXB[(2 + pa) * 256 + xid]);
            fq[pa] = add2(aq[0][pa], EXB[(4 + pa) * 256 + xid]);
        }
    } else {
#pragma unroll
        for (int pa = 0; pa < 2; pa++) {
            fh[pa] = add2(ah[1][pa], EXA[(0 + pa) * 256 + xid]);
            fd[pa] = add2(ad[1][pa], EXA[(2 + pa) * 256 + xid]);
            fq[pa] = add2(aq[1][pa], EXA[(4 + pa) * 256 + xid]);
        }
    }

    // ---- epilogue: 2 rows x 2 paths ----
    const int rbase = j0 + 2 * half;
    float h0[2], h1[2], d0[2], d1[2], q0[2], q1[2];
#pragma unroll
    for (int pa = 0; pa < 2; pa++) {
        upk(fh[pa], h0[pa], h1[pa]);   // lo = row rbase, hi = rbase+1
        upk(fd[pa], d0[pa], d1[pa]);
        upk(fq[pa], q0[pa], q1[pa]);
    }
    ulonglong2* Xn2  = (ulonglong2*)Xn;
    ulonglong2* dXn2 = (ulonglong2*)dXn;
    ulonglong2* QXn2 = (ulonglong2*)QXn;
#pragma unroll
    for (int rr = 0; rr < 2; rr++) {
        int r = rbase + rr;
        int cc = swz(pp, r);
        float sa, ca, sb, cb;
        __sincosf(rr ? h1[0] : h0[0], &sa, &ca);
        __sincosf(rr ? h1[1] : h0[1], &sb, &cb);
        float qsa = __sinf(rr ? q1[0] : q0[0]);
        float qsb = __sinf(rr ? q1[1] : q0[1]);
        float dva = ca * (rr ? d1[0] : d0[0]);
        float dvb = cb * (rr ? d1[1] : d0[1]);
        Xn2[r * 16 + cc]  = make_ulonglong2(pk(sa, sa), pk(sb, sb));
        dXn2[r * 16 + cc] = make_ulonglong2(pk(dva, dva), pk(dvb, dvb));
        QXn2[r * 16 + cc] = make_ulonglong2(pk(qsa, qsa), pk(qsb, qsb));
    }
    __syncthreads();
}

// Fused full-net eval; ends with HD2 partials written and CTA synced.
__device__ __forceinline__ void eval_fused(float* sm, float tval,
                                           int half, int j0, int pp, int jq,
                                           int xid, int wid, int lane, int tid)
{
    const float* netY = sm;
    const float* netQ = sm + NET_SZ;
    float* X   = sm + OFF_X;
    float* dXb = sm + OFF_DX;
    float* Xn  = sm + OFF_XN;
    float* dXn = sm + OFF_DXN;
    float* QX  = sm + OFF_QX;
    float* QXn = sm + OFF_QXN;
    const float* ys = sm + OFF_YS;

    // ---- input layer: thread = 1 row x 4 paths (512 threads cover 64x32/4) --
    {
        int r  = tid & 63;
        int pq = tid >> 6;           // 0..7, paths 4pq..4pq+3
        int p0 = pq * 4;
        float yv[4] = {ys[p0], ys[p0 + 1], ys[p0 + 2], ys[p0 + 3]};
        float wtY = netY[W_IN + r], wyY = netY[W_IN + 64 + r];
        float tbY = fmaf(tval, wtY, netY[B_IN + r]);
        float wtQ = netQ[W_IN + r], wyQ = netQ[W_IN + 64 + r];
        float tbQ = fmaf(tval, wtQ, netQ[B_IN + r]);
        float s[4], c[4], sq[4];
#pragma unroll
        for (int p = 0; p < 4; p++) {
            __sincosf(fmaf(yv[p], wyY, tbY), &s[p], &c[p]);
            sq[p] = __sinf(fmaf(yv[p], wyQ, tbQ));
        }
        ulonglong2* X2  = (ulonglong2*)X;
        ulonglong2* dX2 = (ulonglong2*)dXb;
        ulonglong2* QX2 = (ulonglong2*)QX;
        int cc0 = swz(pq * 2, r), cc1 = swz(pq * 2 + 1, r);
        X2[r * 16 + cc0] = make_ulonglong2(pk(s[0], s[0]), pk(s[1], s[1]));
        X2[r * 16 + cc1] = make_ulonglong2(pk(s[2], s[2]), pk(s[3], s[3]));
        float d0 = c[0] * wyY, d1 = c[1] * wyY, d2 = c[2] * wyY, d3 = c[3] * wyY;
        dX2[r * 16 + cc0] = make_ulonglong2(pk(d0, d0), pk(d1, d1));
        dX2[r * 16 + cc1] = make_ulonglong2(pk(d2, d2), pk(d3, d3));
        QX2[r * 16 + cc0] = make_ulonglong2(pk(sq[0], sq[0]), pk(sq[1], sq[1]));
        QX2[r * 16 + cc1] = make_ulonglong2(pk(sq[2], sq[2]), pk(sq[3], sq[3]));
    }
    __syncthreads();

    fused_layer(sm, netY + W_H,        netY + B_H,       netQ + W_H,        netQ + B_H,
                X, dXb, QX, Xn, dXn, QXn, half, j0, pp, jq, xid);
    fused_layer(sm, netY + W_H + 4096, netY + B_H + 64,  netQ + W_H + 4096, netQ + B_H + 64,
                Xn, dXn, QXn, X, dXb, QX, half, j0, pp, jq, xid);
    fused_layer(sm, netY + W_H + 8192, netY + B_H + 128, netQ + W_H + 8192, netQ + B_H + 128,
                X, dXb, QX, Xn, dXn, QXn, half, j0, pp, jq, xid);

    // ---- head partials: warps 0-5 = (half h2, head) x 32 paths ----
    if (wid < 6) {
        int head = wid % 3, h2 = wid / 3;
        const float* src = (head == 0) ? Xn : (head == 1) ? dXn : QXn;
        const float* wv  = (head == 2) ? (netQ + W_OUT) : (netY + W_OUT);
        int p = lane;
        int i0 = h2 * 32;
        float a0 = 0.0f, a1 = 0.0f, a2 = 0.0f, a3 = 0.0f;
#pragma unroll 4
        for (int i = 0; i < 32; i += 4) {
#pragma unroll
            for (int k = 0; k < 4; k++) {
                int ii = i0 + i + k;
                int off = ii * 64 + swz(p >> 1, ii) * 4 + (p & 1) * 2;
                float v = src[off] * wv[ii];
                if (k == 0) a0 += v; else if (k == 1) a1 += v;
                else if (k == 2) a2 += v; else a3 += v;
            }
        }
        sm[OFF_HD2 + h2 * 96 + head * 32 + p] = (a0 + a1) + (a2 + a3);
    }
    __syncthreads();
}

__global__ __launch_bounds__(NTHR, 1) void fbsnn_main(
    const float* __restrict__ yWin,  const float* __restrict__ yBin,
    const float* __restrict__ yWh,   const float* __restrict__ yBh,
    const float* __restrict__ yWout, const float* __restrict__ yBout,
    const float* __restrict__ qWin,  const float* __restrict__ qBin,
    const float* __restrict__ qWh,   const float* __restrict__ qBh,
    const float* __restrict__ qWout, const float* __restrict__ qBout,
    const float* __restrict__ y0,    const float* __restrict__ dW,
    float* __restrict__ out)
{
    extern __shared__ float sm[];
    const int tid  = threadIdx.x;
    const int wid  = tid >> 5;
    const int lane = tid & 31;
    // warp tile: (half, jwg, pwg); lane tile: (jsub, psub)
    const int half = wid >> 3;          // K-half
    const int jwg  = (wid >> 1) & 3;    // 4 j-warp-groups of 16 rows
    const int pwg  = wid & 1;           // 2 path-warp-groups of 16 paths
    const int jsub = lane >> 3;         // 4 j-quads within warp
    const int psub = lane & 7;          // 8 path-pairs within warp
    const int j0   = jwg * 16 + jsub * 4;
    const int jq   = jwg * 4 + jsub;    // ull2 weight index
    const int pp   = pwg * 8 + psub;    // dup'd 16B chunk (paths 2pp, 2pp+1)
    const int xid  = tid & 255;         // exchange slot (partner = other half)

    // ---- stage all weights into smem once ----
    cpf(sm + W_IN,  yWin, 128,   tid);
    cpf(sm + B_IN,  yBin, 64,    tid);
    cpf(sm + W_H,   yWh,  12288, tid);
    cpf(sm + B_H,   yBh,  192,   tid);
    cpf(sm + W_OUT, yWout, 64,   tid);
    if (tid == 0) sm[B_OUT] = yBout[0];
    float* smq = sm + NET_SZ;
    cpf(smq + W_IN,  qWin, 128,   tid);
    cpf(smq + B_IN,  qBin, 64,    tid);
    cpf(smq + W_H,   qWh,  12288, tid);
    cpf(smq + B_H,   qBh,  192,   tid);
    cpf(smq + W_OUT, qWout, 64,   tid);
    if (tid == 0) smq[B_OUT] = qBout[0];
    if (tid < 32) sm[OFF_YS + tid] = y0[0];
    __syncthreads();

    const int pbase = blockIdx.x * PPC;
    const float* HD2 = sm + OFF_HD2;

    float lossAcc = 0.0f, Ytilde = 0.0f;
    float dwcur = 0.0f;
    if (wid == 0) dwcur = dW[pbase + lane];   // prefetch step 0

    // initial fused eval at t = 0
    eval_fused(sm, 0.0f, half, j0, pp, jq, xid, wid, lane, tid);

    for (int n = 0; n < NSTEP; n++) {
        if (wid == 0) {
            int p = lane;
            float Yv  = HD2[p]      + HD2[96 + p]  + sm[B_OUT];
            float dYv = HD2[32 + p] + HD2[128 + p];
            float qv  = HD2[64 + p] + HD2[160 + p] + smq[B_OUT];
            if (n > 0) {
                float e = Yv - Ytilde;
                lossAcc = fmaf(e, e, lossAcc);
            }
            float dwn = SQRT_DT * dwcur;
            Ytilde = Yv - qv * qv * DTV + SIGMA * dYv * dwn;
            sm[OFF_YS + p] += qv * DTV + SIGMA * dwn;
            if (n + 1 < NSTEP) dwcur = dW[(n + 1) * BATCH + pbase + p];
        }
        __syncthreads();

        eval_fused(sm, (float)(n + 1) * DTV, half, j0, pp, jq, xid, wid, lane, tid);
    }

    if (wid == 0) {
        int p = lane;
        float Yv  = HD2[p]      + HD2[96 + p]  + sm[B_OUT];
        float dYv = HD2[32 + p] + HD2[128 + p];
        float e = Yv - Ytilde;
        lossAcc = fmaf(e, e, lossAcc);
        float yN = sm[OFF_YS + p];
        float e1 = Yv - yN * yN;
        float e2 = dYv - 2.0f * yN;
        lossAcc = fmaf(e1, e1, fmaf(e2, e2, lossAcc));
#pragma unroll
        for (int o = 16; o > 0; o >>= 1)
            lossAcc += __shfl_down_sync(0xffffffffu, lossAcc, o);
        if (lane == 0) g_part[blockIdx.x] = lossAcc;
    }

    // ---- last-CTA deterministic reduction (single launch) ----
    if (tid == 0) {
        __threadfence();
        int old = atomicAdd(&g_count, 1);
        if (old == NCTA - 1) {
            __threadfence();
            float acc = 0.0f;
#pragma unroll 8
            for (int i = 0; i < NCTA; i++) acc += g_part[i];
            out[0] = acc * (1.0f / (float)BATCH);
            g_count = 0;
        }
    }
}

extern "C" void kernel_launch(void* const* d_in, const int* in_sizes, int n_in,
                              void* d_out, int out_size)
{
    const float *yWin, *yBin, *yWh, *yBh, *yWout, *yBout;
    const float *qWin, *qBin, *qWh, *qBh, *qWout, *qBout;
    const float *y0, *dW;

    if (in_sizes[0] == 1) {
        y0    = (const float*)d_in[0];
        yWin  = (const float*)d_in[1];
        yBin  = (const float*)d_in[2];
        yWh   = (const float*)d_in[3];
        yBh   = (const float*)d_in[4];
        yWout = (const float*)d_in[5];
        yBout = (const float*)d_in[6];
        qWin  = (const float*)d_in[7];
        qBin  = (const float*)d_in[8];
        qWh   = (const float*)d_in[9];
        qBh   = (const float*)d_in[10];
        qWout = (const float*)d_in[11];
        qBout = (const float*)d_in[12];
        dW    = (const float*)d_in[13];
    } else {
        yWin  = (const float*)d_in[0];
        yBin  = (const float*)d_in[1];
        yWh   = (const float*)d_in[2];
        yBh   = (const float*)d_in[3];
        yWout = (const float*)d_in[4];
        yBout = (const float*)d_in[5];
        qWin  = (const float*)d_in[6];
        qBin  = (const float*)d_in[7];
        qWh   = (const float*)d_in[8];
        qBh   = (const float*)d_in[9];
        qWout = (const float*)d_in[10];
        qBout = (const float*)d_in[11];
        y0    = (const float*)d_in[12];
        dW    = (const float*)d_in[13];
    }

    cudaFuncSetAttribute(fbsnn_main, cudaFuncAttributeMaxDynamicSharedMemorySize,
                         SMEM_BYTES);

    fbsnn_main<<<NCTA, NTHR, SMEM_BYTES>>>(yWin, yBin, yWh, yBh, yWout, yBout,
                                           qWin, qBin, qWh, qBh, qWout, qBout,
                                           y0, dW, (float*)d_out);
}

// round 7
// speedup vs baseline: 3.1150x; 1.3971x over previous
#include <cuda_runtime.h>

#define DTV      0.02f
#define SQRT_DT  0.141421356237309515f
#define SIGMA    0.5f
#define NSTEP    50
#define BATCH    4096
#define PPC      32            // paths per CTA
#define NCTA     (BATCH / PPC) // 128
#define NTHR     256

typedef unsigned long long u64;

// ---- shared-memory layout (float offsets) ----
#define W_IN   0       // [2][64] = 128
#define B_IN   128     // 64
#define W_H    192     // [3][64][64] = 12288
#define B_H    12480   // [3][64] = 192
#define W_OUT  12672   // 64
#define B_OUT  12736   // 1 (+3 pad)
#define NET_SZ 12740
// activation buffers: NON-duplicated [64 rows][32 paths] floats,
// 8 chunks of 16B per row, chunk-XOR-swizzled: phys = c ^ (r & 7)
#define XBUF     2048
#define OFF_X    (2 * NET_SZ)           // 25480 (16B aligned)
#define OFF_DX   (OFF_X   + XBUF)
#define OFF_XN   (OFF_DX  + XBUF)
#define OFF_DXN  (OFF_XN  + XBUF)
#define OFF_QX   (OFF_DXN + XBUF)
#define OFF_QXN  (OFF_QX  + XBUF)
// K-half exchange: two [12][128] u64 buffers
#define OFF_EXA  (OFF_QXN + XBUF)       // 3072 floats
#define OFF_EXB  (OFF_EXA + 3072)
#define OFF_YS   (OFF_EXB + 3072)
#define OFF_HD2  (OFF_YS  + 32)         // [2 halves][3 heads][32]
#define SMEM_FLOATS (OFF_HD2 + 192)
#define SMEM_BYTES  (SMEM_FLOATS * 4)   // ~176 KB

__device__ float g_part[NCTA];
__device__ int   g_count = 0;

__device__ __forceinline__ void cpf(float* d, const float* s, int n, int tid) {
    for (int i = tid; i < n; i += NTHR) d[i] = s[i];
}

__device__ __forceinline__ u64 fma2(u64 a, u64 b, u64 c) {
    u64 d;
    asm("fma.rn.f32x2 %0, %1, %2, %3;" : "=l"(d) : "l"(a), "l"(b), "l"(c));
    return d;
}
__device__ __forceinline__ u64 add2(u64 a, u64 b) {
    u64 d;
    asm("add.rn.f32x2 %0, %1, %2;" : "=l"(d) : "l"(a), "l"(b));
    return d;
}
__device__ __forceinline__ u64 pk(float lo, float hi) {
    u64 r;
    asm("mov.b64 %0, {%1, %2};" : "=l"(r) : "f"(lo), "f"(hi));
    return r;
}
__device__ __forceinline__ void upk(u64 v, float& lo, float& hi) {
    asm("mov.b64 {%0, %1}, %2;" : "=f"(lo), "=f"(hi) : "l"(v));
}

// chunk swizzle: 8 chunks of 16B per 128B activation row
__device__ __forceinline__ int swz8(int c, int r) { return c ^ (r & 7); }

// Fused hidden layer, path-packed accumulators, K-half split.
// Thread tile: 4 j x 4 paths (2 packed pairs) x {h, dh, q}, half the i-range.
// ah[jj][pr] = {h[j0+jj][4pg+2pr], h[j0+jj][4pg+2pr+1]}
__device__ __forceinline__ void fused_layer(
    float* __restrict__ sm,
    const float* __restrict__ Wy, const float* __restrict__ by,
    const float* __restrict__ Wq, const float* __restrict__ bq,
    const float* __restrict__ X,  const float* __restrict__ dXb,
    const float* __restrict__ QX,
    float* __restrict__ Xn, float* __restrict__ dXn, float* __restrict__ QXn,
    int half, int j0, int pg, int jg, int xid)
{
    const float4* WY4 = (const float4*)Wy;     // 16 float4 per 64-float row
    const float4* WQ4 = (const float4*)Wq;
    const ulonglong2* X2  = (const ulonglong2*)X;   // 8 ull2 per 128B row
    const ulonglong2* dX2 = (const ulonglong2*)dXb;
    const ulonglong2* QX2 = (const ulonglong2*)QX;

    u64 ah[4][2], ad[4][2], aq[4][2];
#pragma unroll
    for (int jj = 0; jj < 4; jj++)
#pragma unroll
        for (int pr = 0; pr < 2; pr++) {
            // bias folded only into the rows this half keeps
            if ((jj >> 1) == half) {
                ah[jj][pr] = pk(by[j0 + jj], by[j0 + jj]);
                aq[jj][pr] = pk(bq[j0 + jj], bq[j0 + jj]);
            } else {
                ah[jj][pr] = 0ull;
                aq[jj][pr] = 0ull;
            }
            ad[jj][pr] = 0ull;
        }

    const int ib = half * 32;
#pragma unroll 4
    for (int k = 0; k < 32; k++) {
        int i = ib + k;
        float4 wy = WY4[i * 16 + jg];
        float4 wq = WQ4[i * 16 + jg];
        int cc = swz8(pg, i);
        ulonglong2 xv = X2[i * 8 + cc];   // {x_p0,x_p1},{x_p2,x_p3}
        ulonglong2 dv = dX2[i * 8 + cc];
        ulonglong2 qv = QX2[i * 8 + cc];
        float wyv[4] = {wy.x, wy.y, wy.z, wy.w};
        float wqv[4] = {wq.x, wq.y, wq.z, wq.w};
#pragma unroll
        for (int jj = 0; jj < 4; jj++) {
            u64 wyp = pk(wyv[jj], wyv[jj]);
            u64 wqp = pk(wqv[jj], wqv[jj]);
            ah[jj][0] = fma2(wyp, xv.x, ah[jj][0]);
            ah[jj][1] = fma2(wyp, xv.y, ah[jj][1]);
            ad[jj][0] = fma2(wyp, dv.x, ad[jj][0]);
            ad[jj][1] = fma2(wyp, dv.y, ad[jj][1]);
            aq[jj][0] = fma2(wqp, qv.x, aq[jj][0]);
            aq[jj][1] = fma2(wqp, qv.y, aq[jj][1]);
        }
    }

    // ---- exchange: give away the 2 rows this half doesn't keep ----
    u64* EXA = (u64*)(sm + OFF_EXA);   // written by half 0
    u64* EXB = (u64*)(sm + OFF_EXB);   // written by half 1
    {
        u64* EXW = half ? EXB : EXA;
        int jgive = half ? 0 : 2;       // rows given away
#pragma unroll
        for (int t = 0; t < 2; t++)
#pragma unroll
            for (int pr = 0; pr < 2; pr++) {
                int s = t * 2 + pr;
                EXW[(0 + s) * 128 + xid] = ah[jgive + t][pr];
                EXW[(4 + s) * 128 + xid] = ad[jgive + t][pr];
                EXW[(8 + s) * 128 + xid] = aq[jgive + t][pr];
            }
    }
    __syncthreads();
    const int jk = half * 2;            // first kept row index (jj)
    {
        const u64* EXR = half ? EXA : EXB;
#pragma unroll
        for (int t = 0; t < 2; t++)
#pragma unroll
            for (int pr = 0; pr < 2; pr++) {
                int s = t * 2 + pr;
                ah[jk + t][pr] = add2(ah[jk + t][pr], EXR[(0 + s) * 128 + xid]);
                ad[jk + t][pr] = add2(ad[jk + t][pr], EXR[(4 + s) * 128 + xid]);
                aq[jk + t][pr] = add2(aq[jk + t][pr], EXR[(8 + s) * 128 + xid]);
            }
    }

    // ---- epilogue: 2 kept rows x 4 paths, non-dup float4 stores ----
    float4* Xn4  = (float4*)Xn;
    float4* dXn4 = (float4*)dXn;
    float4* QXn4 = (float4*)QXn;
#pragma unroll
    for (int t = 0; t < 2; t++) {
        int r = j0 + jk + t;
        float hv[4], dv_[4], qv_[4];
        upk(ah[jk + t][0], hv[0], hv[1]);
        upk(ah[jk + t][1], hv[2], hv[3]);
        upk(ad[jk + t][0], dv_[0], dv_[1]);
        upk(ad[jk + t][1], dv_[2], dv_[3]);
        upk(aq[jk + t][0], qv_[0], qv_[1]);
        upk(aq[jk + t][1], qv_[2], qv_[3]);
        float s[4], c[4], sq[4];
#pragma unroll
        for (int p = 0; p < 4; p++) {
            __sincosf(hv[p], &s[p], &c[p]);
            sq[p] = __sinf(qv_[p]);
        }
        int cc = swz8(pg, r);
        Xn4[r * 8 + cc]  = make_float4(s[0], s[1], s[2], s[3]);
        dXn4[r * 8 + cc] = make_float4(c[0] * dv_[0], c[1] * dv_[1],
                                       c[2] * dv_[2], c[3] * dv_[3]);
        QXn4[r * 8 + cc] = make_float4(sq[0], sq[1], sq[2], sq[3]);
    }
    __syncthreads();
}

// Fused full-net eval; ends with HD2 partials written and CTA synced.
__device__ __forceinline__ void eval_fused(float* sm, float tval,
                                           int half, int j0, int pg, int jg,
                                           int xid, int wid, int lane, int tid)
{
    const float* netY = sm;
    const float* netQ = sm + NET_SZ;
    float* X   = sm + OFF_X;
    float* dXb = sm + OFF_DX;
    float* Xn  = sm + OFF_XN;
    float* dXn = sm + OFF_DXN;
    float* QX  = sm + OFF_QX;
    float* QXn = sm + OFF_QXN;
    const float* ys = sm + OFF_YS;

    // ---- input layer: thread = 1 row x 8 paths (2 chunks) ----
    {
        int r  = tid & 63;
        int c0 = (tid >> 6) * 2;
        float wtY = netY[W_IN + r], wyY = netY[W_IN + 64 + r];
        float tbY = fmaf(tval, wtY, netY[B_IN + r]);
        float wtQ = netQ[W_IN + r], wyQ = netQ[W_IN + 64 + r];
        float tbQ = fmaf(tval, wtQ, netQ[B_IN + r]);
        float4* X4  = (float4*)X;
        float4* dX4 = (float4*)dXb;
        float4* QX4 = (float4*)QX;
#pragma unroll
        for (int u = 0; u < 2; u++) {
            int ch = c0 + u;
            int p0 = ch * 4;
            float s[4], c[4], sq[4];
#pragma unroll
            for (int p = 0; p < 4; p++) {
                __sincosf(fmaf(ys[p0 + p], wyY, tbY), &s[p], &c[p]);
                sq[p] = __sinf(fmaf(ys[p0 + p], wyQ, tbQ));
            }
            int cc = swz8(ch, r);
            X4[r * 8 + cc]  = make_float4(s[0], s[1], s[2], s[3]);
            dX4[r * 8 + cc] = make_float4(c[0] * wyY, c[1] * wyY,
                                          c[2] * wyY, c[3] * wyY);
            QX4[r * 8 + cc] = make_float4(sq[0], sq[1], sq[2], sq[3]);
        }
    }
    __syncthreads();

    fused_layer(sm, netY + W_H,        netY + B_H,       netQ + W_H,        netQ + B_H,
                X, dXb, QX, Xn, dXn, QXn, half, j0, pg, jg, xid);
    fused_layer(sm, netY + W_H + 4096, netY + B_H + 64,  netQ + W_H + 4096, netQ + B_H + 64,
                Xn, dXn, QXn, X, dXb, QX, half, j0, pg, jg, xid);
    fused_layer(sm, netY + W_H + 8192, netY + B_H + 128, netQ + W_H + 8192, netQ + B_H + 128,
                X, dXb, QX, Xn, dXn, QXn, half, j0, pg, jg, xid);

    // ---- head partials: warps 0-5 = (i-half h2, head) x 32 paths ----
    if (wid < 6) {
        int head = wid % 3, h2 = wid / 3;
        const float* src = (head == 0) ? Xn : (head == 1) ? dXn : QXn;
        const float* wv  = (head == 2) ? (netQ + W_OUT) : (netY + W_OUT);
        int p = lane;
        int pch = p >> 2, pin = p & 3;
        int i0 = h2 * 32;
        float a0 = 0.0f, a1 = 0.0f, a2 = 0.0f, a3 = 0.0f;
#pragma unroll 4
        for (int i = 0; i < 32; i += 4) {
#pragma unroll
            for (int k = 0; k < 4; k++) {
                int ii = i0 + i + k;
                int off = ii * 32 + swz8(pch, ii) * 4 + pin;
                float v = src[off] * wv[ii];
                if (k == 0) a0 += v; else if (k == 1) a1 += v;
                else if (k == 2) a2 += v; else a3 += v;
            }
        }
        sm[OFF_HD2 + h2 * 96 + head * 32 + p] = (a0 + a1) + (a2 + a3);
    }
    __syncthreads();
}

__global__ __launch_bounds__(NTHR, 1) void fbsnn_main(
    const float* __restrict__ yWin,  const float* __restrict__ yBin,
    const float* __restrict__ yWh,   const float* __restrict__ yBh,
    const float* __restrict__ yWout, const float* __restrict__ yBout,
    const float* __restrict__ qWin,  const float* __restrict__ qBin,
    const float* __restrict__ qWh,   const float* __restrict__ qBh,
    const float* __restrict__ qWout, const float* __restrict__ qBout,
    const float* __restrict__ y0,    const float* __restrict__ dW,
    float* __restrict__ out)
{
    extern __shared__ float sm[];
    const int tid  = threadIdx.x;
    const int wid  = tid >> 5;
    const int lane = tid & 31;
    const int half = tid >> 7;      // K-half
    const int ht   = tid & 127;
    const int jg   = ht & 15;       // 16 j-groups of 4
    const int pg   = ht >> 4;       // 8 path-quads (16B chunk index)
    const int j0   = jg * 4;
    const int xid  = ht;            // exchange slot

    // ---- stage all weights into smem once ----
    cpf(sm + W_IN,  yWin, 128,   tid);
    cpf(sm + B_IN,  yBin, 64,    tid);
    cpf(sm + W_H,   yWh,  12288, tid);
    cpf(sm + B_H,   yBh,  192,   tid);
    cpf(sm + W_OUT, yWout, 64,   tid);
    if (tid == 0) sm[B_OUT] = yBout[0];
    float* smq = sm + NET_SZ;
    cpf(smq + W_IN,  qWin, 128,   tid);
    cpf(smq + B_IN,  qBin, 64,    tid);
    cpf(smq + W_H,   qWh,  12288, tid);
    cpf(smq + B_H,   qBh,  192,   tid);
    cpf(smq + W_OUT, qWout, 64,   tid);
    if (tid == 0) smq[B_OUT] = qBout[0];
    if (tid < 32) sm[OFF_YS + tid] = y0[0];
    __syncthreads();

    const int pbase = blockIdx.x * PPC;
    const float* HD2 = sm + OFF_HD2;

    float lossAcc = 0.0f, Ytilde = 0.0f;
    float dwcur = 0.0f;
    if (wid == 0) dwcur = dW[pbase + lane];   // prefetch step 0

    // initial fused eval at t = 0
    eval_fused(sm, 0.0f, half, j0, pg, jg, xid, wid, lane, tid);

    for (int n = 0; n < NSTEP; n++) {
        if (wid == 0) {
            int p = lane;
            float Yv  = HD2[p]      + HD2[96 + p]  + sm[B_OUT];
            float dYv = HD2[32 + p] + HD2[128 + p];
            float qv  = HD2[64 + p] + HD2[160 + p] + smq[B_OUT];
            if (n > 0) {
                float e = Yv - Ytilde;
                lossAcc = fmaf(e, e, lossAcc);
            }
            float dwn = SQRT_DT * dwcur;
            Ytilde = Yv - qv * qv * DTV + SIGMA * dYv * dwn;
            sm[OFF_YS + p] += qv * DTV + SIGMA * dwn;
            if (n + 1 < NSTEP) dwcur = dW[(n + 1) * BATCH + pbase + p];
        }
        __syncthreads();

        eval_fused(sm, (float)(n + 1) * DTV, half, j0, pg, jg, xid, wid, lane, tid);
    }

    if (wid == 0) {
        int p = lane;
        float Yv  = HD2[p]      + HD2[96 + p]  + sm[B_OUT];
        float dYv = HD2[32 + p] + HD2[128 + p];
        float e = Yv - Ytilde;
        lossAcc = fmaf(e, e, lossAcc);
        float yN = sm[OFF_YS + p];
        float e1 = Yv - yN * yN;
        float e2 = dYv - 2.0f * yN;
        lossAcc = fmaf(e1, e1, fmaf(e2, e2, lossAcc));
#pragma unroll
        for (int o = 16; o > 0; o >>= 1)
            lossAcc += __shfl_down_sync(0xffffffffu, lossAcc, o);
        if (lane == 0) g_part[blockIdx.x] = lossAcc;
    }

    // ---- last-CTA deterministic reduction (single launch) ----
    if (tid == 0) {
        __threadfence();
        int old = atomicAdd(&g_count, 1);
        if (old == NCTA - 1) {
            __threadfence();
            float acc = 0.0f;
#pragma unroll 8
            for (int i = 0; i < NCTA; i++) acc += g_part[i];
            out[0] = acc * (1.0f / (float)BATCH);
            g_count = 0;
        }
    }
}

extern "C" void kernel_launch(void* const* d_in, const int* in_sizes, int n_in,
                              void* d_out, int out_size)
{
    const float *yWin, *yBin, *yWh, *yBh, *yWout, *yBout;
    const float *qWin, *qBin, *qWh, *qBh, *qWout, *qBout;
    const float *y0, *dW;

    if (in_sizes[0] == 1) {
        y0    = (const float*)d_in[0];
        yWin  = (const float*)d_in[1];
        yBin  = (const float*)d_in[2];
        yWh   = (const float*)d_in[3];
        yBh   = (const float*)d_in[4];
        yWout = (const float*)d_in[5];
        yBout = (const float*)d_in[6];
        qWin  = (const float*)d_in[7];
        qBin  = (const float*)d_in[8];
        qWh   = (const float*)d_in[9];
        qBh   = (const float*)d_in[10];
        qWout = (const float*)d_in[11];
        qBout = (const float*)d_in[12];
        dW    = (const float*)d_in[13];
    } else {
        yWin  = (const float*)d_in[0];
        yBin  = (const float*)d_in[1];
        yWh   = (const float*)d_in[2];
        yBh   = (const float*)d_in[3];
        yWout = (const float*)d_in[4];
        yBout = (const float*)d_in[5];
        qWin  = (const float*)d_in[6];
        qBin  = (const float*)d_in[7];
        qWh   = (const float*)d_in[8];
        qBh   = (const float*)d_in[9];
        qWout = (const float*)d_in[10];
        qBout = (const float*)d_in[11];
        y0    = (const float*)d_in[12];
        dW    = (const float*)d_in[13];
    }

    cudaFuncSetAttribute(fbsnn_main, cudaFuncAttributeMaxDynamicSharedMemorySize,
                         SMEM_BYTES);

    fbsnn_main<<<NCTA, NTHR, SMEM_BYTES>>>(yWin, yBin, yWh, yBh, yWout, yBout,
                                           qWin, qBin, qWh, qBh, qWout, qBout,
                                           y0, dW, (float*)d_out);
}

// round 8
// speedup vs baseline: 3.3646x; 1.0801x over previous
#include <cuda_runtime.h>

#define DTV      0.02f
#define SQRT_DT  0.141421356237309515f
#define SIGMA    0.5f
#define NSTEP    50
#define BATCH    4096
#define PPC      32            // paths per CTA
#define NCTA     (BATCH / PPC) // 128
#define NTHR     256

typedef unsigned long long u64;

// ---- shared-memory layout (float offsets) ----
#define W_IN   0       // [2][64] = 128
#define B_IN   128     // 64
#define W_H    192     // [3][64][64] = 12288
#define B_H    12480   // [3][64] = 192
#define W_OUT  12672   // 64
#define B_OUT  12736   // 1 (+3 pad)
#define NET_SZ 12740
// activations: duplicated pairs {x,x}, [64 rows][32 u64], XOR-swizzled chunks
#define XBUF     4096
#define OFF_X    (2 * NET_SZ)
#define OFF_DX   (OFF_X   + XBUF)
#define OFF_XN   (OFF_DX  + XBUF)
#define OFF_DXN  (OFF_XN  + XBUF)
#define OFF_QX   (OFF_DXN + XBUF)
#define OFF_QXN  (OFF_QX  + XBUF)
// K-split partial exchange buffers: [12][128] u64 each
#define OFF_PX   (OFF_QXN + XBUF)     // A's pair1 partials (3072 floats)
#define OFF_PY   (OFF_PX  + 3072)    // B's pair0 partials
#define OFF_YS   (OFF_PY  + 3072)
#define OFF_HD2  (OFF_YS  + 32)       // [2][96] head partials
#define OFF_HD   (OFF_HD2 + 192)      // 96 floats: Y | dY | q
#define SMEM_FLOATS (OFF_HD + 96)
#define SMEM_BYTES  (SMEM_FLOATS * 4)

__device__ float g_part[NCTA];
__device__ int   g_count = 0;

__device__ __forceinline__ void cpf(float* d, const float* s, int n, int tid) {
    for (int i = tid; i < n; i += NTHR) d[i] = s[i];
}

__device__ __forceinline__ u64 fma2(u64 a, u64 b, u64 c) {
    u64 d;
    asm("fma.rn.f32x2 %0, %1, %2, %3;" : "=l"(d) : "l"(a), "l"(b), "l"(c));
    return d;
}
__device__ __forceinline__ u64 mul2(u64 a, u64 b) {
    u64 d;
    asm("mul.rn.f32x2 %0, %1, %2;" : "=l"(d) : "l"(a), "l"(b));
    return d;
}
__device__ __forceinline__ u64 add2(u64 a, u64 b) {
    u64 d;
    asm("add.rn.f32x2 %0, %1, %2;" : "=l"(d) : "l"(a), "l"(b));
    return d;
}
__device__ __forceinline__ u64 pk(float lo, float hi) {
    u64 r;
    asm("mov.b64 %0, {%1, %2};" : "=l"(r) : "f"(lo), "f"(hi));
    return r;
}
__device__ __forceinline__ void upk(u64 v, float& lo, float& hi) {
    asm("mov.b64 {%0, %1}, %2;" : "=f"(lo), "=f"(hi) : "l"(v));
}

// Packed sin via degree-19 odd Taylor (abs err < 4e-6 for |x| <= 4.8; hidden
// pre-activations are sigma~0.7 so 4.8 = ~7 sigma). Runs on FMA pipe,
// offloading the saturated MUFU pipe. 10 f32x2 ops per pair.
__device__ __forceinline__ u64 sinpoly2(u64 x) {
    u64 u = mul2(x, x);
    u64 p = pk(-8.22063525e-18f, -8.22063525e-18f);          // c19
    p = fma2(p, u, pk( 2.81145725e-15f,  2.81145725e-15f));  // c17
    p = fma2(p, u, pk(-7.64716373e-13f, -7.64716373e-13f));  // c15
    p = fma2(p, u, pk( 1.60590438e-10f,  1.60590438e-10f));  // c13
    p = fma2(p, u, pk(-2.50521084e-8f,  -2.50521084e-8f));   // c11
    p = fma2(p, u, pk( 2.75573192e-6f,   2.75573192e-6f));   // c9
    p = fma2(p, u, pk(-1.98412698e-4f,  -1.98412698e-4f));   // c7
    p = fma2(p, u, pk( 8.33333333e-3f,   8.33333333e-3f));   // c5
    p = fma2(p, u, pk(-1.66666667e-1f,  -1.66666667e-1f));   // c3
    p = fma2(p, u, pk( 1.0f, 1.0f));                          // c1
    return mul2(p, x);
}

// swizzled 16B-chunk index within a 64-row x 256B activation buffer
__device__ __forceinline__ int swz(int c, int r) { return c ^ ((r >> 2) & 15); }

// store 2 rows (rbase, rbase+1) of sin/dsin/q activations from one packed pair
__device__ __forceinline__ void epilogue_rows(
    float* __restrict__ Xn, float* __restrict__ dXn, float* __restrict__ QXn,
    int rbase, int pg, u64 ahp[4], u64 adp[4], u64 aqp[4])
{
    // q-net sine on FMA pipe (packed), Y-net sincos on MUFU
    u64 qs[4];
#pragma unroll
    for (int p = 0; p < 4; p++) qs[p] = sinpoly2(aqp[p]);

    float h0[4], h1[4], d0v[4], d1v[4], q0[4], q1[4];
#pragma unroll
    for (int p = 0; p < 4; p++) {
        upk(ahp[p], h0[p], h1[p]);
        upk(adp[p], d0v[p], d1v[p]);
        upk(qs[p],  q0[p], q1[p]);
    }
    ulonglong2* Xn2  = (ulonglong2*)Xn;
    ulonglong2* dXn2 = (ulonglong2*)dXn;
    ulonglong2* QXn2 = (ulonglong2*)QXn;
#pragma unroll
    for (int rr = 0; rr < 2; rr++) {
        int r = rbase + rr;
        const float* hv = rr ? h1 : h0;
        const float* dv = rr ? d1v : d0v;
        const float* qv = rr ? q1 : q0;
        float s[4], c[4];
#pragma unroll
        for (int p = 0; p < 4; p++) __sincosf(hv[p], &s[p], &c[p]);
        int cc0 = swz(pg * 2, r);
        int cc1 = swz(pg * 2 + 1, r);
        Xn2[r * 16 + cc0] = make_ulonglong2(pk(s[0], s[0]), pk(s[1], s[1]));
        Xn2[r * 16 + cc1] = make_ulonglong2(pk(s[2], s[2]), pk(s[3], s[3]));
        float e0 = c[0] * dv[0], e1 = c[1] * dv[1];
        float e2 = c[2] * dv[2], e3 = c[3] * dv[3];
        dXn2[r * 16 + cc0] = make_ulonglong2(pk(e0, e0), pk(e1, e1));
        dXn2[r * 16 + cc1] = make_ulonglong2(pk(e2, e2), pk(e3, e3));
        QXn2[r * 16 + cc0] = make_ulonglong2(pk(qv[0], qv[0]), pk(qv[1], qv[1]));
        QXn2[r * 16 + cc1] = make_ulonglong2(pk(qv[2], qv[2]), pk(qv[3], qv[3]));
    }
}

// Fused hidden layer, K-split across the two thread halves.
// half A (tid<128): i in [0,32);  half B: i in [32,64).
// Exchange packed partials through smem, each half finishes 2 of its 4 rows.
__device__ __forceinline__ void fused_layer(
    float* __restrict__ sm,
    const float* __restrict__ Wy, const float* __restrict__ by,
    const float* __restrict__ Wq, const float* __restrict__ bq,
    const float* __restrict__ X,  const float* __restrict__ dXb,
    const float* __restrict__ QX,
    float* __restrict__ Xn, float* __restrict__ dXn, float* __restrict__ QXn,
    int jg, int pg, int half, int ht)
{
    const ulonglong2* WY2 = (const ulonglong2*)Wy;
    const ulonglong2* WQ2 = (const ulonglong2*)Wq;
    const ulonglong2* X2  = (const ulonglong2*)X;
    const ulonglong2* dX2 = (const ulonglong2*)dXb;
    const ulonglong2* QX2 = (const ulonglong2*)QX;

    const int j0 = jg * 4;
    const int ib = half * 32;

    u64 ah[2][4], ad[2][4], aq[2][4];
    {
        u64 by01 = pk(by[j0], by[j0 + 1]);
        u64 by23 = pk(by[j0 + 2], by[j0 + 3]);
        u64 bq01 = pk(bq[j0], bq[j0 + 1]);
        u64 bq23 = pk(bq[j0 + 2], bq[j0 + 3]);
#pragma unroll
        for (int p = 0; p < 4; p++) {
            ah[0][p] = half ? 0ull : by01;
            ah[1][p] = half ? by23 : 0ull;
            aq[0][p] = half ? 0ull : bq01;
            aq[1][p] = half ? bq23 : 0ull;
            ad[0][p] = 0ull; ad[1][p] = 0ull;
        }
    }

#pragma unroll 4
    for (int k = 0; k < 32; k++) {
        int i = ib + k;
        ulonglong2 wY = WY2[i * 16 + jg];
        ulonglong2 wQ = WQ2[i * 16 + jg];
        int c0 = swz(pg * 2, i);
        int c1 = swz(pg * 2 + 1, i);
        ulonglong2 xa = X2[i * 16 + c0];
        ulonglong2 xb = X2[i * 16 + c1];
        ulonglong2 da = dX2[i * 16 + c0];
        ulonglong2 db = dX2[i * 16 + c1];
        ulonglong2 qa = QX2[i * 16 + c0];
        ulonglong2 qb = QX2[i * 16 + c1];
        u64 xd[4] = {xa.x, xa.y, xb.x, xb.y};
        u64 dd[4] = {da.x, da.y, db.x, db.y};
        u64 qd[4] = {qa.x, qa.y, qb.x, qb.y};
#pragma unroll
        for (int p = 0; p < 4; p++) {
            ah[0][p] = fma2(wY.x, xd[p], ah[0][p]);
            ah[1][p] = fma2(wY.y, xd[p], ah[1][p]);
            ad[0][p] = fma2(wY.x, dd[p], ad[0][p]);
            ad[1][p] = fma2(wY.y, dd[p], ad[1][p]);
            aq[0][p] = fma2(wQ.x, qd[p], aq[0][p]);
            aq[1][p] = fma2(wQ.y, qd[p], aq[1][p]);
        }
    }

    // ---- partial exchange: A gives pair1, B gives pair0 ----
    u64* PX = (u64*)(sm + OFF_PX);   // written by A
    u64* PY = (u64*)(sm + OFF_PY);   // written by B
    if (half == 0) {
#pragma unroll
        for (int p = 0; p < 4; p++) {
            PX[(0 + p) * 128 + ht] = ah[1][p];
            PX[(4 + p) * 128 + ht] = ad[1][p];
            PX[(8 + p) * 128 + ht] = aq[1][p];
        }
    } else {
#pragma unroll
        for (int p = 0; p < 4; p++) {
            PY[(0 + p) * 128 + ht] = ah[0][p];
            PY[(4 + p) * 128 + ht] = ad[0][p];
            PY[(8 + p) * 128 + ht] = aq[0][p];
        }
    }
    __syncthreads();
    if (half == 0) {
#pragma unroll
        for (int p = 0; p < 4; p++) {
            ah[0][p] = add2(ah[0][p], PY[(0 + p) * 128 + ht]);
            ad[0][p] = add2(ad[0][p], PY[(4 + p) * 128 + ht]);
            aq[0][p] = add2(aq[0][p], PY[(8 + p) * 128 + ht]);
        }
        epilogue_rows(Xn, dXn, QXn, j0, pg, ah[0], ad[0], aq[0]);
    } else {
#pragma unroll
        for (int p = 0; p < 4; p++) {
            ah[1][p] = add2(ah[1][p], PX[(0 + p) * 128 + ht]);
            ad[1][p] = add2(ad[1][p], PX[(4 + p) * 128 + ht]);
            aq[1][p] = add2(aq[1][p], PX[(8 + p) * 128 + ht]);
        }
        epilogue_rows(Xn, dXn, QXn, j0 + 2, pg, ah[1], ad[1], aq[1]);
    }
    __syncthreads();
}

// Fused full-net eval; ends with HD2 partials written and CTA synced.
__device__ __forceinline__ void eval_fused(float* sm, float tval,
                                           int jg, int pg, int half, int ht,
                                           int tid)
{
    const float* netY = sm;
    const float* netQ = sm + NET_SZ;
    float* X   = sm + OFF_X;
    float* dXb = sm + OFF_DX;
    float* Xn  = sm + OFF_XN;
    float* dXn = sm + OFF_DXN;
    float* QX  = sm + OFF_QX;
    float* QXn = sm + OFF_QXN;
    const float* ys = sm + OFF_YS;

    const int j0 = jg * 4, p0 = pg * 4;

    // ---- input layer (MUFU — arguments can exceed poly range) ----
    {
        ulonglong2* X2  = (ulonglong2*)X;
        ulonglong2* dX2 = (ulonglong2*)dXb;
        ulonglong2* QX2 = (ulonglong2*)QX;
        float yv[4] = {ys[p0], ys[p0 + 1], ys[p0 + 2], ys[p0 + 3]};
#pragma unroll
        for (int jj = 0; jj < 2; jj++) {
            int r = j0 + half * 2 + jj;
            float wtY = netY[W_IN + r], wyY = netY[W_IN + 64 + r];
            float tbY = fmaf(tval, wtY, netY[B_IN + r]);
            float wtQ = netQ[W_IN + r], wyQ = netQ[W_IN + 64 + r];
            float tbQ = fmaf(tval, wtQ, netQ[B_IN + r]);
            float s[4], c[4], sq[4];
#pragma unroll
            for (int p = 0; p < 4; p++) {
                __sincosf(fmaf(yv[p], wyY, tbY), &s[p], &c[p]);
                sq[p] = __sinf(fmaf(yv[p], wyQ, tbQ));
            }
            int cc0 = swz(pg * 2, r);
            int cc1 = swz(pg * 2 + 1, r);
            X2[r * 16 + cc0] = make_ulonglong2(pk(s[0], s[0]), pk(s[1], s[1]));
            X2[r * 16 + cc1] = make_ulonglong2(pk(s[2], s[2]), pk(s[3], s[3]));
            float d0 = c[0] * wyY, d1 = c[1] * wyY, d2 = c[2] * wyY, d3 = c[3] * wyY;
            dX2[r * 16 + cc0] = make_ulonglong2(pk(d0, d0), pk(d1, d1));
            dX2[r * 16 + cc1] = make_ulonglong2(pk(d2, d2), pk(d3, d3));
            QX2[r * 16 + cc0] = make_ulonglong2(pk(sq[0], sq[0]), pk(sq[1], sq[1]));
            QX2[r * 16 + cc1] = make_ulonglong2(pk(sq[2], sq[2]), pk(sq[3], sq[3]));
        }
    }
    __syncthreads();
    fused_layer(sm, netY + W_H,        netY + B_H,       netQ + W_H,        netQ + B_H,
                X, dXb, QX, Xn, dXn, QXn, jg, pg, half, ht);
    fused_layer(sm, netY + W_H + 4096, netY + B_H + 64,  netQ + W_H + 4096, netQ + B_H + 64,
                Xn, dXn, QXn, X, dXb, QX, jg, pg, half, ht);
    fused_layer(sm, netY + W_H + 8192, netY + B_H + 128, netQ + W_H + 8192, netQ + B_H + 128,
                X, dXb, QX, Xn, dXn, QXn, jg, pg, half, ht);

    // ---- output heads, i-split: A warps 0-2 do i<32, B warps 4-6 do i>=32 ----
    const int wid = tid >> 5, lane = tid & 31;
    float* HD2 = sm + OFF_HD2;
    float* HD  = sm + OFF_HD;
    int hw = wid & 3;
    if (hw < 3) {
        const float* src = (hw == 0) ? Xn : (hw == 1) ? dXn : QXn;
        const float* wv  = (hw == 2) ? (netQ + W_OUT) : (netY + W_OUT);
        int i0 = half * 32;
        float a0 = 0.0f, a1 = 0.0f, a2 = 0.0f, a3 = 0.0f;
        int p = lane;
#pragma unroll 4
        for (int i = 0; i < 32; i += 4) {
#pragma unroll
            for (int k = 0; k < 4; k++) {
                int ii = i0 + i + k;
                int ch = swz(p >> 1, ii);
                int off = ii * 64 + ch * 4 + (p & 1) * 2;
                float v = src[off] * wv[ii];
                if (k == 0) a0 += v; else if (k == 1) a1 += v;
                else if (k == 2) a2 += v; else a3 += v;
            }
        }
        HD2[half * 96 + hw * 32 + lane] = (a0 + a1) + (a2 + a3);
    }
    __syncthreads();
    if (tid < 96) {
        int head = tid >> 5;
        float bias = (head == 0) ? netY[B_OUT] : (head == 2) ? netQ[B_OUT] : 0.0f;
        HD[tid] = HD2[tid] + HD2[96 + tid] + bias;
    }
    __syncthreads();
}

__global__ __launch_bounds__(NTHR, 1) void fbsnn_main(
    const float* __restrict__ yWin,  const float* __restrict__ yBin,
    const float* __restrict__ yWh,   const float* __restrict__ yBh,
    const float* __restrict__ yWout, const float* __restrict__ yBout,
    const float* __restrict__ qWin,  const float* __restrict__ qBin,
    const float* __restrict__ qWh,   const float* __restrict__ qBh,
    const float* __restrict__ qWout, const float* __restrict__ qBout,
    const float* __restrict__ y0,    const float* __restrict__ dW,
    float* __restrict__ out)
{
    extern __shared__ float sm[];
    const int tid = threadIdx.x;
    const int half = tid >> 7;
    const int ht = tid & 127;
    const int jg = ht & 15;
    const int pg = ht >> 4;

    // ---- stage all weights into smem once ----
    cpf(sm + W_IN,  yWin, 128,   tid);
    cpf(sm + B_IN,  yBin, 64,    tid);
    cpf(sm + W_H,   yWh,  12288, tid);
    cpf(sm + B_H,   yBh,  192,   tid);
    cpf(sm + W_OUT, yWout, 64,   tid);
    if (tid == 0) sm[B_OUT] = yBout[0];
    float* smq = sm + NET_SZ;
    cpf(smq + W_IN,  qWin, 128,   tid);
    cpf(smq + B_IN,  qBin, 64,    tid);
    cpf(smq + W_H,   qWh,  12288, tid);
    cpf(smq + B_H,   qBh,  192,   tid);
    cpf(smq + W_OUT, qWout, 64,   tid);
    if (tid == 0) smq[B_OUT] = qBout[0];
    if (tid < 32) sm[OFF_YS + tid] = y0[0];
    __syncthreads();

    float Yv = 0.0f, lossAcc = 0.0f, Ytilde = 0.0f;
    const int pbase = blockIdx.x * PPC;
    float* HD = sm + OFF_HD;

    // initial fused eval at t = 0: gives Y0, dY0, q0
    eval_fused(sm, 0.0f, jg, pg, half, ht, tid);

    for (int n = 0; n < NSTEP; n++) {
        if (tid < 32) {
            float Yc  = HD[tid];
            float dYv = HD[32 + tid];
            float qv  = HD[64 + tid];
            float dwn = SQRT_DT * dW[n * BATCH + pbase + tid];
            Ytilde = Yc - qv * qv * DTV + SIGMA * dYv * dwn;
            sm[OFF_YS + tid] += qv * DTV + SIGMA * dwn;
        }
        __syncthreads();

        eval_fused(sm, (float)(n + 1) * DTV, jg, pg, half, ht, tid);

        if (tid < 32) {
            float e = HD[tid] - Ytilde;
            lossAcc = fmaf(e, e, lossAcc);
        }
    }

    if (tid < 32) {
        float yN = sm[OFF_YS + tid];
        float e1 = HD[tid]      - yN * yN;   // terminal value residual
        float e2 = HD[32 + tid] - 2.0f * yN; // terminal gradient residual
        lossAcc = fmaf(e1, e1, fmaf(e2, e2, lossAcc));
#pragma unroll
        for (int o = 16; o > 0; o >>= 1)
            lossAcc += __shfl_down_sync(0xffffffffu, lossAcc, o);
        if (tid == 0) g_part[blockIdx.x] = lossAcc;
    }

    // ---- last-CTA deterministic reduction (single-launch design) ----
    if (tid == 0) {
        __threadfence();
        int old = atomicAdd(&g_count, 1);
        if (old == NCTA - 1) {
            __threadfence();
            float acc = 0.0f;
#pragma unroll 8
            for (int i = 0; i < NCTA; i++) acc += g_part[i];
            out[0] = acc * (1.0f / (float)BATCH);
            g_count = 0;
        }
    }
}

extern "C" void kernel_launch(void* const* d_in, const int* in_sizes, int n_in,
                              void* d_out, int out_size)
{
    const float *yWin, *yBin, *yWh, *yBh, *yWout, *yBout;
    const float *qWin, *qBin, *qWh, *qBh, *qWout, *qBout;
    const float *y0, *dW;

    if (in_sizes[0] == 1) {
        y0    = (const float*)d_in[0];
        yWin  = (const float*)d_in[1];
        yBin  = (const float*)d_in[2];
        yWh   = (const float*)d_in[3];
        yBh   = (const float*)d_in[4];
        yWout = (const float*)d_in[5];
        yBout = (const float*)d_in[6];
        qWin  = (const float*)d_in[7];
        qBin  = (const float*)d_in[8];
        qWh   = (const float*)d_in[9];
        qBh   = (const float*)d_in[10];
        qWout = (const float*)d_in[11];
        qBout = (const float*)d_in[12];
        dW    = (const float*)d_in[13];
    } else {
        yWin  = (const float*)d_in[0];
        yBin  = (const float*)d_in[1];
        yWh   = (const float*)d_in[2];
        yBh   = (const float*)d_in[3];
        yWout = (const float*)d_in[4];
        yBout = (const float*)d_in[5];
        qWin  = (const float*)d_in[6];
        qBin  = (const float*)d_in[7];
        qWh   = (const float*)d_in[8];
        qBh   = (const float*)d_in[9];
        qWout = (const float*)d_in[10];
        qBout = (const float*)d_in[11];
        y0    = (const float*)d_in[12];
        dW    = (const float*)d_in[13];
    }

    cudaFuncSetAttribute(fbsnn_main, cudaFuncAttributeMaxDynamicSharedMemorySize,
                         SMEM_BYTES);

    fbsnn_main<<<NCTA, NTHR, SMEM_BYTES>>>(yWin, yBin, yWh, yBh, yWout, yBout,
                                           qWin, qBin, qWh, qBh, qWout, qBout,
                                           y0, dW, (float*)d_out);
}